// round 8
// baseline (speedup 1.0000x reference)
#include <cuda_runtime.h>
#include <math.h>
#include <stdint.h>

#define T_STEPS 512
#define BATCH   64
#define IN_DIM  1024
#define HID     1024
#define BH      (BATCH * HID)          // 65536

// ---------- TF32 helpers ----------
__device__ __forceinline__ uint32_t f2tf32(float f) {
    uint32_t r;
    asm("cvt.rna.tf32.f32 %0, %1;" : "=r"(r) : "f"(f));
    return r;
}

__device__ __forceinline__ float tanh_fast(float x) {
    float y;
    asm("tanh.approx.f32 %0, %1;" : "=f"(y) : "f"(x));
    return y;
}

__device__ __forceinline__ void mma_tf32(float c[4], const uint32_t a[4], const uint32_t b[2]) {
    asm("mma.sync.aligned.m16n8k8.row.col.f32.tf32.tf32.f32 "
        "{%0,%1,%2,%3}, {%4,%5,%6,%7}, {%8,%9}, {%0,%1,%2,%3};\n"
        : "+f"(c[0]), "+f"(c[1]), "+f"(c[2]), "+f"(c[3])
        : "r"(a[0]), "r"(a[1]), "r"(a[2]), "r"(a[3]), "r"(b[0]), "r"(b[1]));
}

// ============================================================
// Kernel 1: Xp = X @ W_xh + b  (TF32 mma; smem holds pre-converted
// tf32 bits) — unchanged from R7.
// ============================================================
#define XA_STRIDE 36
#define XB_STRIDE 72

__global__ __launch_bounds__(256) void xp_gemm_tf32(const float* __restrict__ A,
                                                    const float* __restrict__ B,
                                                    const float* __restrict__ bias,
                                                    float* __restrict__ C) {
    __shared__ uint32_t As[128][XA_STRIDE];
    __shared__ uint32_t Bs[32][XB_STRIDE];
    __shared__ float biasS[64];

    const int bm  = blockIdx.y * 128;
    const int bn  = blockIdx.x * 64;
    const int tid = threadIdx.x;
    const int wid = tid >> 5;
    const int lane = tid & 31;
    const int gr  = lane >> 2;
    const int tg  = lane & 3;
    const int m_warp = wid & 1;
    const int n_warp = wid >> 1;

    if (tid < 64) biasS[tid] = bias[bn + tid];

    float acc[4][2][4] = {};

    for (int k0 = 0; k0 < IN_DIM; k0 += 32) {
        #pragma unroll
        for (int j = 0; j < 4; j++) {
            int idx = tid + j * 256;
            int m   = idx >> 3;
            int kq  = (idx & 7) * 4;
            float4 v = *reinterpret_cast<const float4*>(
                &A[(size_t)(bm + m) * IN_DIM + k0 + kq]);
            uint4 w = make_uint4(f2tf32(v.x), f2tf32(v.y), f2tf32(v.z), f2tf32(v.w));
            *reinterpret_cast<uint4*>(&As[m][kq]) = w;
        }
        #pragma unroll
        for (int j = 0; j < 2; j++) {
            int idx = tid + j * 256;
            int kk  = idx >> 4;
            int nq  = (idx & 15) * 4;
            float4 v = *reinterpret_cast<const float4*>(
                &B[(size_t)(k0 + kk) * HID + bn + nq]);
            uint4 w = make_uint4(f2tf32(v.x), f2tf32(v.y), f2tf32(v.z), f2tf32(v.w));
            *reinterpret_cast<uint4*>(&Bs[kk][nq]) = w;
        }
        __syncthreads();

        #pragma unroll
        for (int ks = 0; ks < 4; ks++) {
            const int k8 = ks * 8;
            uint32_t bf[2][2];
            #pragma unroll
            for (int nt = 0; nt < 2; nt++) {
                int nn = n_warp * 16 + nt * 8 + gr;
                bf[nt][0] = Bs[k8 + tg][nn];
                bf[nt][1] = Bs[k8 + tg + 4][nn];
            }
            #pragma unroll
            for (int mt = 0; mt < 4; mt++) {
                int mb = m_warp * 64 + mt * 16;
                uint32_t af[4];
                af[0] = As[mb + gr][k8 + tg];
                af[1] = As[mb + gr + 8][k8 + tg];
                af[2] = As[mb + gr][k8 + tg + 4];
                af[3] = As[mb + gr + 8][k8 + tg + 4];
                mma_tf32(acc[mt][0], af, bf[0]);
                mma_tf32(acc[mt][1], af, bf[1]);
            }
        }
        __syncthreads();
    }

    #pragma unroll
    for (int mt = 0; mt < 4; mt++) {
        #pragma unroll
        for (int nt = 0; nt < 2; nt++) {
            int colL = n_warp * 16 + nt * 8 + 2 * tg;
            int row0 = bm + m_warp * 64 + mt * 16 + gr;
            float2 v0, v1;
            v0.x = acc[mt][nt][0] + biasS[colL];
            v0.y = acc[mt][nt][1] + biasS[colL + 1];
            v1.x = acc[mt][nt][2] + biasS[colL];
            v1.y = acc[mt][nt][3] + biasS[colL + 1];
            *reinterpret_cast<float2*>(&C[(size_t)row0 * HID + bn + colL]) = v0;
            *reinterpret_cast<float2*>(&C[(size_t)(row0 + 8) * HID + bn + colL]) = v1;
        }
    }
}

// ============================================================
// Persistent scan kernel — R7 structure, NEW distributed-counter
// grid barrier: 16 counters 128B apart (parallel L2 slices) kill
// the 128-way single-address atomic serialization.
// ============================================================
#define SC_BLOCKS 128
#define SC_KS     8
#define SC_KSL    128
#define H_STRIDE  144   // 144 mod 32 == 16 -> conflict-free LDS.128

#define NCTR       16
#define CTR_STRIDE 32   // u32 units -> 128 B between counters

__device__ float    g_partial[SC_KS * BH];     // 2 MB scratch
__device__ unsigned g_cnt[NCTR * CTR_STRIDE];  // distributed barrier counters
__device__ unsigned g_done = 0;

__device__ __forceinline__ void grid_bar(unsigned* round, int nblocks, int bid) {
    __syncthreads();
    (*round)++;
    if (threadIdx.x == 0) {
        unsigned target = (unsigned)nblocks * (*round);
        // release-arrival on this block's counter (bid&15) — publishes
        // this block's prior global stores.
        asm volatile("red.release.gpu.global.add.u32 [%0], %1;"
                     :: "l"(&g_cnt[(bid & (NCTR - 1)) * CTR_STRIDE]), "r"(1u)
                     : "memory");
        unsigned s;
        int spins = 0;
        do {
            s = 0;
            #pragma unroll
            for (int i = 0; i < NCTR; i++) {
                unsigned v;
                asm volatile("ld.relaxed.gpu.global.u32 %0, [%1];"
                             : "=r"(v) : "l"(&g_cnt[i * CTR_STRIDE]) : "memory");
                s += v;
            }
            if (++spins > 2048) __nanosleep(64);
        } while (s < target);
        // Upgrade the relaxed observation: pairs with the release-arrivals.
        asm volatile("fence.acq_rel.gpu;" ::: "memory");
    }
    __syncthreads();
}

__global__ __launch_bounds__(256, 1) void rnn_scan(const float* __restrict__ W,
                                                   float* __restrict__ out) {
    __shared__ uint32_t hs[64][H_STRIDE];   // 36.9 KB, tf32 bits [b][k]

    const int tid  = threadIdx.x;
    const int bid  = blockIdx.x;
    const int ks   = bid >> 4;
    const int nb   = bid & 15;
    const int k_base = ks * SC_KSL;
    const int n_base = nb * 64;
    const int wid  = tid >> 5;
    const int lane = tid & 31;
    const int gr   = lane >> 2;
    const int tg   = lane & 3;
    const int m_warp = wid & 1;
    const int n_warp = wid >> 1;

    // ---- W_hh B-fragments, permuted-K indexing, once for 512 steps ----
    uint32_t bfr[8][2][2][2];
    #pragma unroll
    for (int u = 0; u < 8; u++) {
        #pragma unroll
        for (int p = 0; p < 2; p++) {
            #pragma unroll
            for (int nt = 0; nt < 2; nt++) {
                int n = n_base + n_warp * 16 + nt * 8 + gr;
                int kk = k_base + 16 * u + 4 * tg + 2 * p;
                bfr[u][p][nt][0] = f2tf32(W[(size_t)kk * HID + n]);
                bfr[u][p][nt][1] = f2tf32(W[(size_t)(kk + 1) * HID + n]);
            }
        }
    }

    unsigned round = 0;
    const int pb2 = (bid * 256 + tid) * 2;
    const int pb4 = (bid * 128 + tid) * 4;

    // ---- Step 0: h_0 = tanh(Xp_0) ----
    {
        float2 v = *reinterpret_cast<float2*>(&out[pb2]);
        v.x = tanh_fast(v.x);
        v.y = tanh_fast(v.y);
        *reinterpret_cast<float2*>(&out[pb2]) = v;
    }
    grid_bar(&round, SC_BLOCKS, bid);

    for (int t = 1; t < T_STEPS; t++) {
        const float* h = out + (size_t)(t - 1) * BH;
        float* o       = out + (size_t)t * BH;

        // ---- Stage h slice [64b x 128k], converting to tf32 ----
        #pragma unroll
        for (int j = 0; j < 8; j++) {
            int idx = tid + j * 256;
            int b   = idx >> 5;
            int kq  = (idx & 31) * 4;
            float4 v = *reinterpret_cast<const float4*>(
                &h[(size_t)b * HID + k_base + kq]);
            uint4 w = make_uint4(f2tf32(v.x), f2tf32(v.y), f2tf32(v.z), f2tf32(v.w));
            *reinterpret_cast<uint4*>(&hs[b][kq]) = w;
        }
        __syncthreads();

        // ---- 64 mma/warp, A-frags via LDS.128 (permuted K) ----
        float acc[2][2][4] = {};
        #pragma unroll
        for (int u = 0; u < 8; u++) {
            const int kc = 16 * u + 4 * tg;
            #pragma unroll
            for (int mt = 0; mt < 2; mt++) {
                int row = m_warp * 32 + mt * 16 + gr;
                uint4 va = *reinterpret_cast<const uint4*>(&hs[row][kc]);
                uint4 vb = *reinterpret_cast<const uint4*>(&hs[row + 8][kc]);
                uint32_t afA[4] = {va.x, vb.x, va.y, vb.y};
                uint32_t afB[4] = {va.z, vb.z, va.w, vb.w};
                mma_tf32(acc[mt][0], afA, bfr[u][0][0]);
                mma_tf32(acc[mt][1], afA, bfr[u][0][1]);
                mma_tf32(acc[mt][0], afB, bfr[u][1][0]);
                mma_tf32(acc[mt][1], afB, bfr[u][1][1]);
            }
        }

        // ---- Store partials ----
        float* gp = &g_partial[ks * BH];
        #pragma unroll
        for (int mt = 0; mt < 2; mt++) {
            #pragma unroll
            for (int nt = 0; nt < 2; nt++) {
                int colL = n_base + n_warp * 16 + nt * 8 + 2 * tg;
                int row0 = m_warp * 32 + mt * 16 + gr;
                float2 v0 = make_float2(acc[mt][nt][0], acc[mt][nt][1]);
                float2 v1 = make_float2(acc[mt][nt][2], acc[mt][nt][3]);
                *reinterpret_cast<float2*>(&gp[(size_t)row0 * HID + colL]) = v0;
                *reinterpret_cast<float2*>(&gp[(size_t)(row0 + 8) * HID + colL]) = v1;
            }
        }

        // ---- Prefetch Xp_t (half threads, float4); materialize pre-arrival ----
        float4 xp = make_float4(0.f, 0.f, 0.f, 0.f);
        if (tid < 128) {
            xp = *reinterpret_cast<const float4*>(&o[pb4]);
            asm volatile("" : "+f"(xp.x), "+f"(xp.y), "+f"(xp.z), "+f"(xp.w));
        }

        grid_bar(&round, SC_BLOCKS, bid);

        // ---- Phase B: reduce 8 partials + Xp, tanh, write out[t] ----
        if (tid < 128) {
            float s0 = xp.x, s1 = xp.y, s2 = xp.z, s3 = xp.w;
            #pragma unroll
            for (int k2 = 0; k2 < SC_KS; k2++) {
                float4 p = *reinterpret_cast<const float4*>(&g_partial[k2 * BH + pb4]);
                s0 += p.x; s1 += p.y; s2 += p.z; s3 += p.w;
            }
            float4 r;
            r.x = tanh_fast(s0);
            r.y = tanh_fast(s1);
            r.z = tanh_fast(s2);
            r.w = tanh_fast(s3);
            *reinterpret_cast<float4*>(&o[pb4]) = r;
        }
        grid_bar(&round, SC_BLOCKS, bid);
    }

    // ---- Final state = out[T-1] -> tail ----
    {
        float2 v = *reinterpret_cast<const float2*>(
            &out[(size_t)(T_STEPS - 1) * BH + pb2]);
        *reinterpret_cast<float2*>(&out[(size_t)T_STEPS * BH + pb2]) = v;
    }

    // ---- Reset barrier state for graph replays ----
    __syncthreads();
    if (tid == 0) {
        unsigned d = atomicAdd(&g_done, 1u);
        if (d == (unsigned)(gridDim.x - 1)) {
            #pragma unroll
            for (int i = 0; i < NCTR; i++) g_cnt[i * CTR_STRIDE] = 0;
            g_done = 0;
            __threadfence();
        }
    }
}

// ============================================================
extern "C" void kernel_launch(void* const* d_in, const int* in_sizes, int n_in,
                              void* d_out, int out_size) {
    const float* X    = (const float*)d_in[0];
    const float* W_xh = (const float*)d_in[1];
    const float* W_hh = (const float*)d_in[2];
    const float* b_h  = (const float*)d_in[3];
    float* out = (float*)d_out;

    {
        dim3 grid(HID / 64, (T_STEPS * BATCH) / 128);
        xp_gemm_tf32<<<grid, 256>>>(X, W_xh, b_h, out);
    }
    rnn_scan<<<SC_BLOCKS, 256>>>(W_hh, out);
}